// round 2
// baseline (speedup 1.0000x reference)
#include <cuda_runtime.h>

#define NN 50000
#define EE 800000
#define FF 128
#define HH 128
#define HH2 64
#define TT 8
#define GG 64

// scratch (static device allocations are allowed)
__device__ __align__(16) float g_deg[NN];
__device__ __align__(16) float g_dinv[NN];
__device__ __align__(16) float g_hs[NN * HH];     // (x@W) * dinv[row]
__device__ __align__(16) float g_acc[NN * HH];    // running aggregation
__device__ __align__(16) float g_pooled[GG * HH]; // per-group sums of relu(...)

__device__ __forceinline__ void red4(float* p, float4 v) {
    asm volatile("red.global.add.v4.f32 [%0], {%1,%2,%3,%4};"
                 :: "l"(p), "f"(v.x), "f"(v.y), "f"(v.z), "f"(v.w) : "memory");
}

// -------------------------------------------------------------------------
__global__ void k_init() {
    int i = blockIdx.x * blockDim.x + threadIdx.x;
    if (i < NN) g_deg[i] = 1.0f;           // self-loop
    if (i < GG * HH) g_pooled[i] = 0.0f;
}

__global__ void k_deg(const int* __restrict__ ei) {
    int e = blockIdx.x * blockDim.x + threadIdx.x;
    if (e < EE) atomicAdd(&g_deg[ei[EE + e]], 1.0f);
}

__global__ void k_dinv() {
    int i = blockIdx.x * blockDim.x + threadIdx.x;
    if (i < NN) g_dinv[i] = rsqrtf(g_deg[i]);
}

// -------------------------------------------------------------------------
// hs = (x @ W) * dinv[row];  acc initialized to hs (self-loop term)
#define BM 64
#define BK 32
__global__ __launch_bounds__(256) void k_gemm(const float* __restrict__ x,
                                              const float* __restrict__ W) {
    __shared__ float sxT[BK][BM];   // transposed x tile
    __shared__ float sw[BK][HH];
    int tid = threadIdx.x;
    int ty = tid >> 5;      // 0..7  (row group)
    int tx = tid & 31;      // 0..31 (col group)
    int row0 = blockIdx.x * BM;

    float acc[8][4];
#pragma unroll
    for (int i = 0; i < 8; i++)
#pragma unroll
        for (int j = 0; j < 4; j++) acc[i][j] = 0.0f;

    for (int k0 = 0; k0 < FF; k0 += BK) {
        // x tile: 64 rows x 32 cols = 512 float4, 2 per thread
#pragma unroll
        for (int q = 0; q < 2; q++) {
            int idx = tid * 2 + q;          // 0..511
            int r = idx >> 3;               // 0..63
            int c4 = idx & 7;               // 0..7
            float4 v = make_float4(0.f, 0.f, 0.f, 0.f);
            int gr = row0 + r;
            if (gr < NN) v = *(const float4*)(x + (size_t)gr * FF + k0 + c4 * 4);
            sxT[c4 * 4 + 0][r] = v.x;
            sxT[c4 * 4 + 1][r] = v.y;
            sxT[c4 * 4 + 2][r] = v.z;
            sxT[c4 * 4 + 3][r] = v.w;
        }
        // W tile: 32 rows x 128 cols = 1024 float4, 4 per thread
#pragma unroll
        for (int q = 0; q < 4; q++) {
            int idx = tid + q * 256;        // 0..1023
            int r = idx >> 5;               // 0..31
            int c4 = idx & 31;              // 0..31
            *(float4*)(&sw[r][c4 * 4]) =
                *(const float4*)(W + (size_t)(k0 + r) * HH + c4 * 4);
        }
        __syncthreads();
#pragma unroll
        for (int k = 0; k < BK; k++) {
            float4 a0 = *(const float4*)(&sxT[k][ty * 8]);
            float4 a1 = *(const float4*)(&sxT[k][ty * 8 + 4]);
            float4 w4 = *(const float4*)(&sw[k][tx * 4]);
            float a[8] = {a0.x, a0.y, a0.z, a0.w, a1.x, a1.y, a1.z, a1.w};
            float wv[4] = {w4.x, w4.y, w4.z, w4.w};
#pragma unroll
            for (int i = 0; i < 8; i++)
#pragma unroll
                for (int j = 0; j < 4; j++) acc[i][j] += a[i] * wv[j];
        }
        __syncthreads();
    }
#pragma unroll
    for (int i = 0; i < 8; i++) {
        int r = row0 + ty * 8 + i;
        if (r < NN) {
            float d = g_dinv[r];
            float4 v = make_float4(acc[i][0] * d, acc[i][1] * d,
                                   acc[i][2] * d, acc[i][3] * d);
            *(float4*)(g_hs + (size_t)r * HH + tx * 4) = v;
            *(float4*)(g_acc + (size_t)r * HH + tx * 4) = v;
        }
    }
}

// -------------------------------------------------------------------------
// one warp per edge: acc[dst] += hs[src]  (norm folded into hs + final dinv)
__global__ __launch_bounds__(256) void k_scatter(const int* __restrict__ ei) {
    int t = blockIdx.x * blockDim.x + threadIdx.x;
    int e = t >> 5;
    if (e >= EE) return;
    int lane = threadIdx.x & 31;
    int src = __ldg(ei + e);
    int dst = __ldg(ei + EE + e);
    float4 v = *(const float4*)(g_hs + (size_t)src * HH + lane * 4);
    red4(g_acc + (size_t)dst * HH + lane * 4, v);
}

// -------------------------------------------------------------------------
// pooled[g] += relu(acc[n]*dinv[n] + b) — batch sorted, so register-accumulate
// per warp and only flush on group change.
#define CHUNK 512
__global__ __launch_bounds__(256) void k_pool(const int* __restrict__ batch,
                                              const float* __restrict__ b) {
    int w = threadIdx.x >> 5;
    int lane = threadIdx.x & 31;
    int n0 = blockIdx.x * CHUNK;
    float4 bb = *(const float4*)(b + lane * 4);
    float4 racc = make_float4(0.f, 0.f, 0.f, 0.f);
    int gcur = -1;
    int nend = n0 + CHUNK;
    if (nend > NN) nend = NN;
    for (int n = n0 + w; n < nend; n += 8) {
        int g = batch[n];
        if (g != gcur) {
            if (gcur >= 0) red4(g_pooled + (size_t)gcur * HH + lane * 4, racc);
            gcur = g;
            racc = make_float4(0.f, 0.f, 0.f, 0.f);
        }
        float d = g_dinv[n];
        float4 a = *(const float4*)(g_acc + (size_t)n * HH + lane * 4);
        racc.x += fmaxf(a.x * d + bb.x, 0.f);
        racc.y += fmaxf(a.y * d + bb.y, 0.f);
        racc.z += fmaxf(a.z * d + bb.z, 0.f);
        racc.w += fmaxf(a.w * d + bb.w, 0.f);
    }
    if (gcur >= 0) red4(g_pooled + (size_t)gcur * HH + lane * 4, racc);
}

// -------------------------------------------------------------------------
// mean -> fc1+relu -> actor softmax + critic.  Single block.
__global__ __launch_bounds__(256) void k_head(const int* __restrict__ batch,
                                              const float* __restrict__ fc1_w,
                                              const float* __restrict__ fc1_b,
                                              const float* __restrict__ aw,
                                              const float* __restrict__ ab,
                                              const float* __restrict__ cw,
                                              const float* __restrict__ cb,
                                              float* __restrict__ out) {
    __shared__ float s_gs[GG * HH];       // 32 KB
    __shared__ float s_z[GG * HH2];       // 16 KB
    __shared__ float s_logit[GG * TT];    // 2 KB
    __shared__ int s_lb[GG + 1];
    int tid = threadIdx.x;

    // group boundaries by binary search over sorted batch
    if (tid <= GG) {
        int g = tid, lo = 0, hi = NN;
        while (lo < hi) {
            int mid = (lo + hi) >> 1;
            if (batch[mid] < g) lo = mid + 1; else hi = mid;
        }
        s_lb[tid] = lo;
    }
    __syncthreads();

    for (int i = tid; i < GG * HH; i += 256) {
        int g = i >> 7;
        float c = (float)(s_lb[g + 1] - s_lb[g]);
        s_gs[i] = g_pooled[i] / fmaxf(c, 1.0f);
    }
    __syncthreads();

    // z = relu(gs @ fc1_w + fc1_b): 64x64 outputs
    for (int o = tid; o < GG * HH2; o += 256) {
        int g = o >> 6, j = o & 63;
        float s = fc1_b[j];
        const float* gr = &s_gs[g * HH];
#pragma unroll 8
        for (int k = 0; k < HH; k++) s += gr[k] * fc1_w[k * HH2 + j];
        s_z[o] = fmaxf(s, 0.f);
    }
    __syncthreads();

    // logits = z @ actor_w + actor_b : 512 outputs (FIXED: strided loop,
    // previous version only covered the first 256 with a guard)
    for (int o = tid; o < GG * TT; o += 256) {
        int g = o >> 3, t = o & 7;
        float s = ab[t];
        const float* zr = &s_z[g * HH2];
#pragma unroll
        for (int k = 0; k < HH2; k++) s += zr[k] * aw[k * TT + t];
        s_logit[o] = s;
    }
    // value = z @ critic_w + critic_b : 64 outputs
    if (tid < GG) {
        float s = cb[0];
        const float* zr = &s_z[tid * HH2];
#pragma unroll
        for (int k = 0; k < HH2; k++) s += zr[k] * cw[k];
        out[GG * TT + tid] = s;
    }
    __syncthreads();

    // softmax over T=8, one thread per group
    if (tid < GG) {
        float m = -1e30f;
#pragma unroll
        for (int t = 0; t < TT; t++) m = fmaxf(m, s_logit[tid * TT + t]);
        float e[TT], sum = 0.f;
#pragma unroll
        for (int t = 0; t < TT; t++) { e[t] = expf(s_logit[tid * TT + t] - m); sum += e[t]; }
        float inv = 1.0f / sum;
#pragma unroll
        for (int t = 0; t < TT; t++) out[tid * TT + t] = e[t] * inv;
    }
}

// -------------------------------------------------------------------------
extern "C" void kernel_launch(void* const* d_in, const int* in_sizes, int n_in,
                              void* d_out, int out_size) {
    const float* x     = (const float*)d_in[0];
    const int*   ei    = (const int*)d_in[1];
    const int*   batch = (const int*)d_in[2];
    const float* W     = (const float*)d_in[3];
    const float* b     = (const float*)d_in[4];
    const float* fc1_w = (const float*)d_in[5];
    const float* fc1_b = (const float*)d_in[6];
    const float* aw    = (const float*)d_in[7];
    const float* ab    = (const float*)d_in[8];
    const float* cw    = (const float*)d_in[9];
    const float* cb    = (const float*)d_in[10];
    float* out = (float*)d_out;

    k_init<<<(NN + 255) / 256, 256>>>();
    k_deg<<<(EE + 255) / 256, 256>>>(ei);
    k_dinv<<<(NN + 255) / 256, 256>>>();
    k_gemm<<<(NN + BM - 1) / BM, 256>>>(x, W);
    k_scatter<<<(EE * 32 + 255) / 256, 256>>>(ei);
    k_pool<<<(NN + CHUNK - 1) / CHUNK, 256>>>(batch, b);
    k_head<<<1, 256>>>(batch, fc1_w, fc1_b, aw, ab, cw, cb, out);
}

// round 3
// speedup vs baseline: 1.0711x; 1.0711x over previous
#include <cuda_runtime.h>

#define NN 50000
#define EE 800000
#define FF 128
#define HH 128
#define HH2 64
#define TT 8
#define GG 64

// scratch (static device allocations are allowed)
__device__ __align__(16) float g_dinv[NN];
__device__ __align__(16) float g_hs[NN * HH];     // (x@W) * dinv[row]
__device__ __align__(16) float g_pooled[GG * HH]; // per-group sums of relu(...)
__device__ int g_cnt[NN];          // in-degree (excl self-loop)
__device__ int g_cursor[NN];       // fill cursors
__device__ int g_rowptr[NN + 1];   // CSR row pointers (by dst)
__device__ int g_col[EE];          // CSR column indices (src nodes)

__device__ __forceinline__ void red4(float* p, float4 v) {
    asm volatile("red.global.add.v4.f32 [%0], {%1,%2,%3,%4};"
                 :: "l"(p), "f"(v.x), "f"(v.y), "f"(v.z), "f"(v.w) : "memory");
}

// -------------------------------------------------------------------------
__global__ void k_init() {
    int i = blockIdx.x * blockDim.x + threadIdx.x;
    if (i < NN) { g_cnt[i] = 0; g_cursor[i] = 0; }
    if (i < GG * HH) g_pooled[i] = 0.0f;
}

__global__ void k_count(const int* __restrict__ ei) {
    int e = blockIdx.x * blockDim.x + threadIdx.x;
    if (e < EE) atomicAdd(&g_cnt[ei[EE + e]], 1);
}

__global__ void k_dinv() {
    int i = blockIdx.x * blockDim.x + threadIdx.x;
    if (i < NN) g_dinv[i] = rsqrtf((float)(g_cnt[i] + 1));  // +1 self-loop
}

// single-block exclusive scan of g_cnt -> g_rowptr
__global__ __launch_bounds__(1024) void k_scan() {
    __shared__ int ssum[1024];
    int tid = threadIdx.x;
    const int CH = (NN + 1023) / 1024;  // 49
    int base = tid * CH;
    int s = 0;
    for (int i = 0; i < CH; i++) {
        int idx = base + i;
        s += (idx < NN) ? g_cnt[idx] : 0;
    }
    ssum[tid] = s;
    __syncthreads();
    // Kogge-Stone inclusive scan
    for (int off = 1; off < 1024; off <<= 1) {
        int v = (tid >= off) ? ssum[tid - off] : 0;
        __syncthreads();
        ssum[tid] += v;
        __syncthreads();
    }
    int excl = (tid == 0) ? 0 : ssum[tid - 1];
    for (int i = 0; i < CH; i++) {
        int idx = base + i;
        if (idx < NN) {
            g_rowptr[idx] = excl;
            excl += g_cnt[idx];
        }
    }
    if (tid == 1023) g_rowptr[NN] = ssum[1023];
}

__global__ void k_fill(const int* __restrict__ ei) {
    int e = blockIdx.x * blockDim.x + threadIdx.x;
    if (e < EE) {
        int dst = ei[EE + e];
        int pos = g_rowptr[dst] + atomicAdd(&g_cursor[dst], 1);
        g_col[pos] = ei[e];
    }
}

// -------------------------------------------------------------------------
// hs = (x @ W) * dinv[row]
#define BM 64
#define BK 32
__global__ __launch_bounds__(256) void k_gemm(const float* __restrict__ x,
                                              const float* __restrict__ W) {
    __shared__ float sxT[BK][BM];   // transposed x tile
    __shared__ float sw[BK][HH];
    int tid = threadIdx.x;
    int ty = tid >> 5;      // 0..7  (row group)
    int tx = tid & 31;      // 0..31 (col group)
    int row0 = blockIdx.x * BM;

    float acc[8][4];
#pragma unroll
    for (int i = 0; i < 8; i++)
#pragma unroll
        for (int j = 0; j < 4; j++) acc[i][j] = 0.0f;

    for (int k0 = 0; k0 < FF; k0 += BK) {
#pragma unroll
        for (int q = 0; q < 2; q++) {
            int idx = tid * 2 + q;          // 0..511
            int r = idx >> 3;               // 0..63
            int c4 = idx & 7;               // 0..7
            float4 v = make_float4(0.f, 0.f, 0.f, 0.f);
            int gr = row0 + r;
            if (gr < NN) v = *(const float4*)(x + (size_t)gr * FF + k0 + c4 * 4);
            sxT[c4 * 4 + 0][r] = v.x;
            sxT[c4 * 4 + 1][r] = v.y;
            sxT[c4 * 4 + 2][r] = v.z;
            sxT[c4 * 4 + 3][r] = v.w;
        }
#pragma unroll
        for (int q = 0; q < 4; q++) {
            int idx = tid + q * 256;        // 0..1023
            int r = idx >> 5;               // 0..31
            int c4 = idx & 31;              // 0..31
            *(float4*)(&sw[r][c4 * 4]) =
                *(const float4*)(W + (size_t)(k0 + r) * HH + c4 * 4);
        }
        __syncthreads();
#pragma unroll
        for (int k = 0; k < BK; k++) {
            float4 a0 = *(const float4*)(&sxT[k][ty * 8]);
            float4 a1 = *(const float4*)(&sxT[k][ty * 8 + 4]);
            float4 w4 = *(const float4*)(&sw[k][tx * 4]);
            float a[8] = {a0.x, a0.y, a0.z, a0.w, a1.x, a1.y, a1.z, a1.w};
            float wv[4] = {w4.x, w4.y, w4.z, w4.w};
#pragma unroll
            for (int i = 0; i < 8; i++)
#pragma unroll
                for (int j = 0; j < 4; j++) acc[i][j] += a[i] * wv[j];
        }
        __syncthreads();
    }
#pragma unroll
    for (int i = 0; i < 8; i++) {
        int r = row0 + ty * 8 + i;
        if (r < NN) {
            float d = g_dinv[r];
            *(float4*)(g_hs + (size_t)r * HH + tx * 4) =
                make_float4(acc[i][0] * d, acc[i][1] * d,
                            acc[i][2] * d, acc[i][3] * d);
        }
    }
}

// -------------------------------------------------------------------------
// CSR gather + fused pool: one warp per dst node.
// acc = hs[n] + sum_{src in CSR[n]} hs[src]; p = relu(acc*dinv[n] + b);
// pooled[batch[n]] += p
__global__ __launch_bounds__(256) void k_gather(const int* __restrict__ batch,
                                                const float* __restrict__ b) {
    int w = (blockIdx.x * blockDim.x + threadIdx.x) >> 5;
    if (w >= NN) return;
    int lane = threadIdx.x & 31;
    const float* hrow = g_hs + (size_t)w * HH + lane * 4;
    float4 a0 = *(const float4*)hrow;          // self-loop term
    float4 a1 = make_float4(0.f, 0.f, 0.f, 0.f);
    int beg = g_rowptr[w], end = g_rowptr[w + 1];
    int e = beg;
    for (; e + 2 <= end; e += 2) {
        int s0 = __ldg(g_col + e);
        int s1 = __ldg(g_col + e + 1);
        float4 v0 = *(const float4*)(g_hs + (size_t)s0 * HH + lane * 4);
        float4 v1 = *(const float4*)(g_hs + (size_t)s1 * HH + lane * 4);
        a0.x += v0.x; a0.y += v0.y; a0.z += v0.z; a0.w += v0.w;
        a1.x += v1.x; a1.y += v1.y; a1.z += v1.z; a1.w += v1.w;
    }
    if (e < end) {
        int s0 = __ldg(g_col + e);
        float4 v0 = *(const float4*)(g_hs + (size_t)s0 * HH + lane * 4);
        a0.x += v0.x; a0.y += v0.y; a0.z += v0.z; a0.w += v0.w;
    }
    float d = g_dinv[w];
    float4 bb = *(const float4*)(b + lane * 4);
    float4 p;
    p.x = fmaxf((a0.x + a1.x) * d + bb.x, 0.f);
    p.y = fmaxf((a0.y + a1.y) * d + bb.y, 0.f);
    p.z = fmaxf((a0.z + a1.z) * d + bb.z, 0.f);
    p.w = fmaxf((a0.w + a1.w) * d + bb.w, 0.f);
    int g = __ldg(batch + w);
    red4(g_pooled + (size_t)g * HH + lane * 4, p);
}

// -------------------------------------------------------------------------
// mean -> fc1+relu -> actor softmax + critic.  Single block.
__global__ __launch_bounds__(256) void k_head(const int* __restrict__ batch,
                                              const float* __restrict__ fc1_w,
                                              const float* __restrict__ fc1_b,
                                              const float* __restrict__ aw,
                                              const float* __restrict__ ab,
                                              const float* __restrict__ cw,
                                              const float* __restrict__ cb,
                                              float* __restrict__ out) {
    __shared__ float s_gs[GG * HH];       // 32 KB
    __shared__ float s_z[GG * HH2];       // 16 KB
    __shared__ float s_logit[GG * TT];    // 2 KB
    __shared__ int s_lb[GG + 1];
    int tid = threadIdx.x;

    if (tid <= GG) {
        int g = tid, lo = 0, hi = NN;
        while (lo < hi) {
            int mid = (lo + hi) >> 1;
            if (batch[mid] < g) lo = mid + 1; else hi = mid;
        }
        s_lb[tid] = lo;
    }
    __syncthreads();

    for (int i = tid; i < GG * HH; i += 256) {
        int g = i >> 7;
        float c = (float)(s_lb[g + 1] - s_lb[g]);
        s_gs[i] = g_pooled[i] / fmaxf(c, 1.0f);
    }
    __syncthreads();

    for (int o = tid; o < GG * HH2; o += 256) {
        int g = o >> 6, j = o & 63;
        float s = fc1_b[j];
        const float* gr = &s_gs[g * HH];
#pragma unroll 8
        for (int k = 0; k < HH; k++) s += gr[k] * fc1_w[k * HH2 + j];
        s_z[o] = fmaxf(s, 0.f);
    }
    __syncthreads();

    for (int o = tid; o < GG * TT; o += 256) {
        int g = o >> 3, t = o & 7;
        float s = ab[t];
        const float* zr = &s_z[g * HH2];
#pragma unroll
        for (int k = 0; k < HH2; k++) s += zr[k] * aw[k * TT + t];
        s_logit[o] = s;
    }
    if (tid < GG) {
        float s = cb[0];
        const float* zr = &s_z[tid * HH2];
#pragma unroll
        for (int k = 0; k < HH2; k++) s += zr[k] * cw[k];
        out[GG * TT + tid] = s;
    }
    __syncthreads();

    if (tid < GG) {
        float m = -1e30f;
#pragma unroll
        for (int t = 0; t < TT; t++) m = fmaxf(m, s_logit[tid * TT + t]);
        float e[TT], sum = 0.f;
#pragma unroll
        for (int t = 0; t < TT; t++) { e[t] = expf(s_logit[tid * TT + t] - m); sum += e[t]; }
        float inv = 1.0f / sum;
#pragma unroll
        for (int t = 0; t < TT; t++) out[tid * TT + t] = e[t] * inv;
    }
}

// -------------------------------------------------------------------------
extern "C" void kernel_launch(void* const* d_in, const int* in_sizes, int n_in,
                              void* d_out, int out_size) {
    const float* x     = (const float*)d_in[0];
    const int*   ei    = (const int*)d_in[1];
    const int*   batch = (const int*)d_in[2];
    const float* W     = (const float*)d_in[3];
    const float* b     = (const float*)d_in[4];
    const float* fc1_w = (const float*)d_in[5];
    const float* fc1_b = (const float*)d_in[6];
    const float* aw    = (const float*)d_in[7];
    const float* ab    = (const float*)d_in[8];
    const float* cw    = (const float*)d_in[9];
    const float* cb    = (const float*)d_in[10];
    float* out = (float*)d_out;

    k_init<<<(NN + 255) / 256, 256>>>();
    k_count<<<(EE + 255) / 256, 256>>>(ei);
    k_dinv<<<(NN + 255) / 256, 256>>>();
    k_scan<<<1, 1024>>>();
    k_fill<<<(EE + 255) / 256, 256>>>(ei);
    k_gemm<<<(NN + BM - 1) / BM, 256>>>(x, W);
    k_gather<<<(NN * 32 + 255) / 256, 256>>>(batch, b);
    k_head<<<1, 256>>>(batch, fc1_w, fc1_b, aw, ab, cw, cb, out);
}

// round 5
// speedup vs baseline: 1.4089x; 1.3155x over previous
#include <cuda_runtime.h>

#define NN 50000
#define EE 800000
#define FF 128
#define HH 128
#define HH2 64
#define TT 8
#define GG 64

#define SCAN_B 1024
#define SCAN_NB ((NN + SCAN_B - 1) / SCAN_B)   // 49

// scratch (static device allocations are allowed)
__device__ __align__(16) float g_dinv[NN];
__device__ __align__(16) float g_hs[NN * HH];     // (x@W) * dinv[row]
__device__ __align__(16) float g_pooled[GG * HH]; // per-group sums of relu(...)
__device__ int g_cnt[NN];          // in-degree (excl self-loop)
__device__ int g_cursor[NN];       // fill cursors
__device__ int g_rowptr[NN + 1];   // CSR row pointers (by dst)
__device__ int g_col[EE];          // CSR column indices (src nodes)
__device__ int g_bsum[SCAN_NB];    // per-tile totals -> exclusive offsets

__device__ __forceinline__ void red4(float* p, float4 v) {
    asm volatile("red.global.add.v4.f32 [%0], {%1,%2,%3,%4};"
                 :: "l"(p), "f"(v.x), "f"(v.y), "f"(v.z), "f"(v.w) : "memory");
}

// -------------------------------------------------------------------------
__global__ void k_init() {
    int i = blockIdx.x * blockDim.x + threadIdx.x;
    if (i < NN) { g_cnt[i] = 0; g_cursor[i] = 0; }
    if (i < GG * HH) g_pooled[i] = 0.0f;
}

__global__ void k_count(const int* __restrict__ ei) {
    int e = blockIdx.x * blockDim.x + threadIdx.x;
    if (e < EE) atomicAdd(&g_cnt[ei[EE + e]], 1);
}

// ---- hierarchical scan -------------------------------------------------
// A: per-tile local exclusive scan (+ dinv computation, free ride)
__global__ __launch_bounds__(SCAN_B) void k_scanA() {
    __shared__ int ssum[SCAN_B];
    int tid = threadIdx.x;
    int idx = blockIdx.x * SCAN_B + tid;
    int c = (idx < NN) ? g_cnt[idx] : 0;
    if (idx < NN) g_dinv[idx] = rsqrtf((float)(c + 1));   // +1 self-loop
    ssum[tid] = c;
    __syncthreads();
#pragma unroll
    for (int off = 1; off < SCAN_B; off <<= 1) {
        int v = (tid >= off) ? ssum[tid - off] : 0;
        __syncthreads();
        ssum[tid] += v;
        __syncthreads();
    }
    if (idx < NN) g_rowptr[idx] = ssum[tid] - c;          // local exclusive
    if (tid == SCAN_B - 1) g_bsum[blockIdx.x] = ssum[tid];
}

// B: scan the tile totals (tiny)
__global__ __launch_bounds__(64) void k_scanB() {
    __shared__ int s[SCAN_NB];
    int tid = threadIdx.x;
    if (tid < SCAN_NB) s[tid] = g_bsum[tid];
    __syncthreads();
    if (tid == 0) {
        int run = 0;
        for (int i = 0; i < SCAN_NB; i++) {
            int v = s[i];
            s[i] = run;
            run += v;
        }
        g_rowptr[NN] = run;   // total == EE
    }
    __syncthreads();
    if (tid < SCAN_NB) g_bsum[tid] = s[tid];
}

// C: add tile offsets
__global__ __launch_bounds__(SCAN_B) void k_scanC() {
    int idx = blockIdx.x * SCAN_B + threadIdx.x;
    if (idx < NN && blockIdx.x > 0) g_rowptr[idx] += g_bsum[blockIdx.x];
}

__global__ void k_fill(const int* __restrict__ ei) {
    int e = blockIdx.x * blockDim.x + threadIdx.x;
    if (e < EE) {
        int dst = ei[EE + e];
        int pos = g_rowptr[dst] + atomicAdd(&g_cursor[dst], 1);
        g_col[pos] = ei[e];
    }
}

// -------------------------------------------------------------------------
// hs = (x @ W) * dinv[row]
#define BM 64
#define BK 32
__global__ __launch_bounds__(256) void k_gemm(const float* __restrict__ x,
                                              const float* __restrict__ W) {
    __shared__ float sxT[BK][BM];   // transposed x tile
    __shared__ float sw[BK][HH];
    int tid = threadIdx.x;
    int ty = tid >> 5;      // 0..7  (row group)
    int tx = tid & 31;      // 0..31 (col group)
    int row0 = blockIdx.x * BM;

    float acc[8][4];
#pragma unroll
    for (int i = 0; i < 8; i++)
#pragma unroll
        for (int j = 0; j < 4; j++) acc[i][j] = 0.0f;

    for (int k0 = 0; k0 < FF; k0 += BK) {
#pragma unroll
        for (int q = 0; q < 2; q++) {
            int idx = tid * 2 + q;          // 0..511
            int r = idx >> 3;               // 0..63
            int c4 = idx & 7;               // 0..7
            float4 v = make_float4(0.f, 0.f, 0.f, 0.f);
            int gr = row0 + r;
            if (gr < NN) v = *(const float4*)(x + (size_t)gr * FF + k0 + c4 * 4);
            sxT[c4 * 4 + 0][r] = v.x;
            sxT[c4 * 4 + 1][r] = v.y;
            sxT[c4 * 4 + 2][r] = v.z;
            sxT[c4 * 4 + 3][r] = v.w;
        }
#pragma unroll
        for (int q = 0; q < 4; q++) {
            int idx = tid + q * 256;        // 0..1023
            int r = idx >> 5;               // 0..31
            int c4 = idx & 31;              // 0..31
            *(float4*)(&sw[r][c4 * 4]) =
                *(const float4*)(W + (size_t)(k0 + r) * HH + c4 * 4);
        }
        __syncthreads();
#pragma unroll
        for (int k = 0; k < BK; k++) {
            float4 a0 = *(const float4*)(&sxT[k][ty * 8]);
            float4 a1 = *(const float4*)(&sxT[k][ty * 8 + 4]);
            float4 w4 = *(const float4*)(&sw[k][tx * 4]);
            float a[8] = {a0.x, a0.y, a0.z, a0.w, a1.x, a1.y, a1.z, a1.w};
            float wv[4] = {w4.x, w4.y, w4.z, w4.w};
#pragma unroll
            for (int i = 0; i < 8; i++)
#pragma unroll
                for (int j = 0; j < 4; j++) acc[i][j] += a[i] * wv[j];
        }
        __syncthreads();
    }
#pragma unroll
    for (int i = 0; i < 8; i++) {
        int r = row0 + ty * 8 + i;
        if (r < NN) {
            float d = g_dinv[r];
            *(float4*)(g_hs + (size_t)r * HH + tx * 4) =
                make_float4(acc[i][0] * d, acc[i][1] * d,
                            acc[i][2] * d, acc[i][3] * d);
        }
    }
}

// -------------------------------------------------------------------------
// CSR gather + fused pool: one warp per dst node.
__global__ __launch_bounds__(256) void k_gather(const int* __restrict__ batch,
                                                const float* __restrict__ b) {
    int w = (blockIdx.x * blockDim.x + threadIdx.x) >> 5;
    if (w >= NN) return;
    int lane = threadIdx.x & 31;
    const float* hrow = g_hs + (size_t)w * HH + lane * 4;
    float4 a0 = *(const float4*)hrow;          // self-loop term
    float4 a1 = make_float4(0.f, 0.f, 0.f, 0.f);
    int beg = g_rowptr[w], end = g_rowptr[w + 1];
    int e = beg;
    for (; e + 2 <= end; e += 2) {
        int s0 = __ldg(g_col + e);
        int s1 = __ldg(g_col + e + 1);
        float4 v0 = *(const float4*)(g_hs + (size_t)s0 * HH + lane * 4);
        float4 v1 = *(const float4*)(g_hs + (size_t)s1 * HH + lane * 4);
        a0.x += v0.x; a0.y += v0.y; a0.z += v0.z; a0.w += v0.w;
        a1.x += v1.x; a1.y += v1.y; a1.z += v1.z; a1.w += v1.w;
    }
    if (e < end) {
        int s0 = __ldg(g_col + e);
        float4 v0 = *(const float4*)(g_hs + (size_t)s0 * HH + lane * 4);
        a0.x += v0.x; a0.y += v0.y; a0.z += v0.z; a0.w += v0.w;
    }
    float d = g_dinv[w];
    float4 bb = *(const float4*)(b + lane * 4);
    float4 p;
    p.x = fmaxf((a0.x + a1.x) * d + bb.x, 0.f);
    p.y = fmaxf((a0.y + a1.y) * d + bb.y, 0.f);
    p.z = fmaxf((a0.z + a1.z) * d + bb.z, 0.f);
    p.w = fmaxf((a0.w + a1.w) * d + bb.w, 0.f);
    int g = __ldg(batch + w);
    red4(g_pooled + (size_t)g * HH + lane * 4, p);
}

// -------------------------------------------------------------------------
// mean -> fc1+relu -> actor softmax + critic.  Single block.
__global__ __launch_bounds__(256) void k_head(const int* __restrict__ batch,
                                              const float* __restrict__ fc1_w,
                                              const float* __restrict__ fc1_b,
                                              const float* __restrict__ aw,
                                              const float* __restrict__ ab,
                                              const float* __restrict__ cw,
                                              const float* __restrict__ cb,
                                              float* __restrict__ out) {
    __shared__ float s_gs[GG * HH];       // 32 KB
    __shared__ float s_z[GG * HH2];       // 16 KB
    __shared__ float s_logit[GG * TT];    // 2 KB
    __shared__ int s_lb[GG + 1];
    int tid = threadIdx.x;

    if (tid <= GG) {
        int g = tid, lo = 0, hi = NN;
        while (lo < hi) {
            int mid = (lo + hi) >> 1;
            if (batch[mid] < g) lo = mid + 1; else hi = mid;
        }
        s_lb[tid] = lo;
    }
    __syncthreads();

    for (int i = tid; i < GG * HH; i += 256) {
        int g = i >> 7;
        float c = (float)(s_lb[g + 1] - s_lb[g]);
        s_gs[i] = g_pooled[i] / fmaxf(c, 1.0f);
    }
    __syncthreads();

    for (int o = tid; o < GG * HH2; o += 256) {
        int g = o >> 6, j = o & 63;
        float s = fc1_b[j];
        const float* gr = &s_gs[g * HH];
#pragma unroll 8
        for (int k = 0; k < HH; k++) s += gr[k] * fc1_w[k * HH2 + j];
        s_z[o] = fmaxf(s, 0.f);
    }
    __syncthreads();

    for (int o = tid; o < GG * TT; o += 256) {
        int g = o >> 3, t = o & 7;
        float s = ab[t];
        const float* zr = &s_z[g * HH2];
#pragma unroll
        for (int k = 0; k < HH2; k++) s += zr[k] * aw[k * TT + t];
        s_logit[o] = s;
    }
    if (tid < GG) {
        float s = cb[0];
        const float* zr = &s_z[tid * HH2];
#pragma unroll
        for (int k = 0; k < HH2; k++) s += zr[k] * cw[k];
        out[GG * TT + tid] = s;
    }
    __syncthreads();

    if (tid < GG) {
        float m = -1e30f;
#pragma unroll
        for (int t = 0; t < TT; t++) m = fmaxf(m, s_logit[tid * TT + t]);
        float e[TT], sum = 0.f;
#pragma unroll
        for (int t = 0; t < TT; t++) { e[t] = expf(s_logit[tid * TT + t] - m); sum += e[t]; }
        float inv = 1.0f / sum;
#pragma unroll
        for (int t = 0; t < TT; t++) out[tid * TT + t] = e[t] * inv;
    }
}

// -------------------------------------------------------------------------
extern "C" void kernel_launch(void* const* d_in, const int* in_sizes, int n_in,
                              void* d_out, int out_size) {
    const float* x     = (const float*)d_in[0];
    const int*   ei    = (const int*)d_in[1];
    const int*   batch = (const int*)d_in[2];
    const float* W     = (const float*)d_in[3];
    const float* b     = (const float*)d_in[4];
    const float* fc1_w = (const float*)d_in[5];
    const float* fc1_b = (const float*)d_in[6];
    const float* aw    = (const float*)d_in[7];
    const float* ab    = (const float*)d_in[8];
    const float* cw    = (const float*)d_in[9];
    const float* cb    = (const float*)d_in[10];
    float* out = (float*)d_out;

    k_init<<<(NN + 255) / 256, 256>>>();
    k_count<<<(EE + 255) / 256, 256>>>(ei);
    k_scanA<<<SCAN_NB, SCAN_B>>>();
    k_scanB<<<1, 64>>>();
    k_scanC<<<SCAN_NB, SCAN_B>>>();
    k_fill<<<(EE + 255) / 256, 256>>>(ei);
    k_gemm<<<(NN + BM - 1) / BM, 256>>>(x, W);
    k_gather<<<(NN * 32 + 255) / 256, 256>>>(batch, b);
    k_head<<<1, 256>>>(batch, fc1_w, fc1_b, aw, ab, cw, cb, out);
}

// round 6
// speedup vs baseline: 1.5731x; 1.1165x over previous
#include <cuda_runtime.h>
#include <cuda_fp16.h>

#define NN 50000
#define EE 800000
#define FF 128
#define HH 128
#define HH2 64
#define TT 8
#define GG 64

#define SCAN_B 1024
#define SCAN_NB ((NN + SCAN_B - 1) / SCAN_B)   // 49

// scratch (static device allocations are allowed)
__device__ __align__(16) float  g_dinv[NN];
__device__ __align__(16) __half g_hsh[NN * HH];   // (x@W)*dinv[row] in fp16
__device__ __align__(16) float  g_pooled[GG * HH];
__device__ int g_cnt[NN];
__device__ int g_cursor[NN];
__device__ int g_rowptr[NN + 1];
__device__ int g_col[EE];
__device__ int g_bsum[SCAN_NB];

__device__ __forceinline__ void red4(float* p, float4 v) {
    asm volatile("red.global.add.v4.f32 [%0], {%1,%2,%3,%4};"
                 :: "l"(p), "f"(v.x), "f"(v.y), "f"(v.z), "f"(v.w) : "memory");
}

// -------------------------------------------------------------------------
__global__ void k_init() {
    int i = blockIdx.x * blockDim.x + threadIdx.x;
    if (i < NN) { g_cnt[i] = 0; g_cursor[i] = 0; }
    if (i < GG * HH) g_pooled[i] = 0.0f;
}

__global__ void k_count(const int* __restrict__ ei) {
    int e = blockIdx.x * blockDim.x + threadIdx.x;
    if (e < EE) atomicAdd(&g_cnt[ei[EE + e]], 1);
}

// ---- hierarchical scan -------------------------------------------------
__global__ __launch_bounds__(SCAN_B) void k_scanA() {
    __shared__ int ssum[SCAN_B];
    int tid = threadIdx.x;
    int idx = blockIdx.x * SCAN_B + tid;
    int c = (idx < NN) ? g_cnt[idx] : 0;
    if (idx < NN) g_dinv[idx] = rsqrtf((float)(c + 1));   // +1 self-loop
    ssum[tid] = c;
    __syncthreads();
#pragma unroll
    for (int off = 1; off < SCAN_B; off <<= 1) {
        int v = (tid >= off) ? ssum[tid - off] : 0;
        __syncthreads();
        ssum[tid] += v;
        __syncthreads();
    }
    if (idx < NN) g_rowptr[idx] = ssum[tid] - c;          // local exclusive
    if (tid == SCAN_B - 1) g_bsum[blockIdx.x] = ssum[tid];
}

__global__ __launch_bounds__(64) void k_scanB() {
    __shared__ int s[SCAN_NB];
    int tid = threadIdx.x;
    if (tid < SCAN_NB) s[tid] = g_bsum[tid];
    __syncthreads();
    if (tid == 0) {
        int run = 0;
        for (int i = 0; i < SCAN_NB; i++) { int v = s[i]; s[i] = run; run += v; }
        g_rowptr[NN] = run;
    }
    __syncthreads();
    if (tid < SCAN_NB) g_bsum[tid] = s[tid];
}

__global__ __launch_bounds__(SCAN_B) void k_scanC() {
    int idx = blockIdx.x * SCAN_B + threadIdx.x;
    if (idx < NN && blockIdx.x > 0) g_rowptr[idx] += g_bsum[blockIdx.x];
}

__global__ void k_fill(const int* __restrict__ ei) {
    int e = blockIdx.x * blockDim.x + threadIdx.x;
    if (e < EE) {
        int dst = ei[EE + e];
        int pos = g_rowptr[dst] + atomicAdd(&g_cursor[dst], 1);
        g_col[pos] = ei[e];
    }
}

// -------------------------------------------------------------------------
// hs = (x @ W) * dinv[row], stored as fp16
#define BM 64
#define BK 32
__global__ __launch_bounds__(256) void k_gemm(const float* __restrict__ x,
                                              const float* __restrict__ W) {
    __shared__ float sxT[BK][BM];
    __shared__ float sw[BK][HH];
    int tid = threadIdx.x;
    int ty = tid >> 5;
    int tx = tid & 31;
    int row0 = blockIdx.x * BM;

    float acc[8][4];
#pragma unroll
    for (int i = 0; i < 8; i++)
#pragma unroll
        for (int j = 0; j < 4; j++) acc[i][j] = 0.0f;

    for (int k0 = 0; k0 < FF; k0 += BK) {
#pragma unroll
        for (int q = 0; q < 2; q++) {
            int idx = tid * 2 + q;
            int r = idx >> 3;
            int c4 = idx & 7;
            float4 v = make_float4(0.f, 0.f, 0.f, 0.f);
            int gr = row0 + r;
            if (gr < NN) v = *(const float4*)(x + (size_t)gr * FF + k0 + c4 * 4);
            sxT[c4 * 4 + 0][r] = v.x;
            sxT[c4 * 4 + 1][r] = v.y;
            sxT[c4 * 4 + 2][r] = v.z;
            sxT[c4 * 4 + 3][r] = v.w;
        }
#pragma unroll
        for (int q = 0; q < 4; q++) {
            int idx = tid + q * 256;
            int r = idx >> 5;
            int c4 = idx & 31;
            *(float4*)(&sw[r][c4 * 4]) =
                *(const float4*)(W + (size_t)(k0 + r) * HH + c4 * 4);
        }
        __syncthreads();
#pragma unroll
        for (int k = 0; k < BK; k++) {
            float4 a0 = *(const float4*)(&sxT[k][ty * 8]);
            float4 a1 = *(const float4*)(&sxT[k][ty * 8 + 4]);
            float4 w4 = *(const float4*)(&sw[k][tx * 4]);
            float a[8] = {a0.x, a0.y, a0.z, a0.w, a1.x, a1.y, a1.z, a1.w};
            float wv[4] = {w4.x, w4.y, w4.z, w4.w};
#pragma unroll
            for (int i = 0; i < 8; i++)
#pragma unroll
                for (int j = 0; j < 4; j++) acc[i][j] += a[i] * wv[j];
        }
        __syncthreads();
    }
#pragma unroll
    for (int i = 0; i < 8; i++) {
        int r = row0 + ty * 8 + i;
        if (r < NN) {
            float d = g_dinv[r];
            union { uint2 u; __half2 h[2]; } pk;
            pk.h[0] = __floats2half2_rn(acc[i][0] * d, acc[i][1] * d);
            pk.h[1] = __floats2half2_rn(acc[i][2] * d, acc[i][3] * d);
            *(uint2*)(g_hsh + (size_t)r * HH + tx * 4) = pk.u;
        }
    }
}

// -------------------------------------------------------------------------
// CSR gather + fused pool: one warp per dst node, fp16 operands, fp32 acc.
__global__ __launch_bounds__(256) void k_gather(const int* __restrict__ batch,
                                                const float* __restrict__ b) {
    int w = (blockIdx.x * blockDim.x + threadIdx.x) >> 5;
    if (w >= NN) return;
    int lane = threadIdx.x & 31;
    size_t coff = (size_t)lane * 4;

    // self-loop term
    uint2 us = __ldg((const uint2*)(g_hsh + (size_t)w * HH + coff));
    __half2 hs0 = *(__half2*)&us.x, hs1 = *(__half2*)&us.y;
    float2 f0 = __half22float2(hs0), f1 = __half22float2(hs1);
    float4 a0 = make_float4(f0.x, f0.y, f1.x, f1.y);
    float4 a1 = make_float4(0.f, 0.f, 0.f, 0.f);

    int beg = g_rowptr[w], end = g_rowptr[w + 1];
    int e = beg;
    for (; e + 2 <= end; e += 2) {
        int s0 = __ldg(g_col + e);
        int s1 = __ldg(g_col + e + 1);
        uint2 u0 = __ldg((const uint2*)(g_hsh + (size_t)s0 * HH + coff));
        uint2 u1 = __ldg((const uint2*)(g_hsh + (size_t)s1 * HH + coff));
        float2 p0 = __half22float2(*(__half2*)&u0.x);
        float2 p1 = __half22float2(*(__half2*)&u0.y);
        float2 q0 = __half22float2(*(__half2*)&u1.x);
        float2 q1 = __half22float2(*(__half2*)&u1.y);
        a0.x += p0.x; a0.y += p0.y; a0.z += p1.x; a0.w += p1.y;
        a1.x += q0.x; a1.y += q0.y; a1.z += q1.x; a1.w += q1.y;
    }
    if (e < end) {
        int s0 = __ldg(g_col + e);
        uint2 u0 = __ldg((const uint2*)(g_hsh + (size_t)s0 * HH + coff));
        float2 p0 = __half22float2(*(__half2*)&u0.x);
        float2 p1 = __half22float2(*(__half2*)&u0.y);
        a0.x += p0.x; a0.y += p0.y; a0.z += p1.x; a0.w += p1.y;
    }
    float d = g_dinv[w];
    float4 bb = *(const float4*)(b + coff);
    float4 p;
    p.x = fmaxf((a0.x + a1.x) * d + bb.x, 0.f);
    p.y = fmaxf((a0.y + a1.y) * d + bb.y, 0.f);
    p.z = fmaxf((a0.z + a1.z) * d + bb.z, 0.f);
    p.w = fmaxf((a0.w + a1.w) * d + bb.w, 0.f);
    int g = __ldg(batch + w);
    red4(g_pooled + (size_t)g * HH + coff, p);
}

// -------------------------------------------------------------------------
__global__ __launch_bounds__(256) void k_head(const int* __restrict__ batch,
                                              const float* __restrict__ fc1_w,
                                              const float* __restrict__ fc1_b,
                                              const float* __restrict__ aw,
                                              const float* __restrict__ ab,
                                              const float* __restrict__ cw,
                                              const float* __restrict__ cb,
                                              float* __restrict__ out) {
    __shared__ float s_gs[GG * HH];
    __shared__ float s_z[GG * HH2];
    __shared__ float s_logit[GG * TT];
    __shared__ int s_lb[GG + 1];
    int tid = threadIdx.x;

    if (tid <= GG) {
        int g = tid, lo = 0, hi = NN;
        while (lo < hi) {
            int mid = (lo + hi) >> 1;
            if (batch[mid] < g) lo = mid + 1; else hi = mid;
        }
        s_lb[tid] = lo;
    }
    __syncthreads();

    for (int i = tid; i < GG * HH; i += 256) {
        int g = i >> 7;
        float c = (float)(s_lb[g + 1] - s_lb[g]);
        s_gs[i] = g_pooled[i] / fmaxf(c, 1.0f);
    }
    __syncthreads();

    for (int o = tid; o < GG * HH2; o += 256) {
        int g = o >> 6, j = o & 63;
        float s = fc1_b[j];
        const float* gr = &s_gs[g * HH];
#pragma unroll 8
        for (int k = 0; k < HH; k++) s += gr[k] * fc1_w[k * HH2 + j];
        s_z[o] = fmaxf(s, 0.f);
    }
    __syncthreads();

    for (int o = tid; o < GG * TT; o += 256) {
        int g = o >> 3, t = o & 7;
        float s = ab[t];
        const float* zr = &s_z[g * HH2];
#pragma unroll
        for (int k = 0; k < HH2; k++) s += zr[k] * aw[k * TT + t];
        s_logit[o] = s;
    }
    if (tid < GG) {
        float s = cb[0];
        const float* zr = &s_z[tid * HH2];
#pragma unroll
        for (int k = 0; k < HH2; k++) s += zr[k] * cw[k];
        out[GG * TT + tid] = s;
    }
    __syncthreads();

    if (tid < GG) {
        float m = -1e30f;
#pragma unroll
        for (int t = 0; t < TT; t++) m = fmaxf(m, s_logit[tid * TT + t]);
        float e[TT], sum = 0.f;
#pragma unroll
        for (int t = 0; t < TT; t++) { e[t] = expf(s_logit[tid * TT + t] - m); sum += e[t]; }
        float inv = 1.0f / sum;
#pragma unroll
        for (int t = 0; t < TT; t++) out[tid * TT + t] = e[t] * inv;
    }
}

// -------------------------------------------------------------------------
extern "C" void kernel_launch(void* const* d_in, const int* in_sizes, int n_in,
                              void* d_out, int out_size) {
    const float* x     = (const float*)d_in[0];
    const int*   ei    = (const int*)d_in[1];
    const int*   batch = (const int*)d_in[2];
    const float* W     = (const float*)d_in[3];
    const float* b     = (const float*)d_in[4];
    const float* fc1_w = (const float*)d_in[5];
    const float* fc1_b = (const float*)d_in[6];
    const float* aw    = (const float*)d_in[7];
    const float* ab    = (const float*)d_in[8];
    const float* cw    = (const float*)d_in[9];
    const float* cb    = (const float*)d_in[10];
    float* out = (float*)d_out;

    // Fork-join: CSR build (depends only on ei) overlaps with GEMM
    // (depends only on x, W, dinv... note dinv IS needed by gemm epilogue,
    // and dinv is produced by k_scanA in the CSR chain — so gemm must wait
    // for scanA. Split the chains accordingly: side stream does
    // count -> scanA (produces dinv); main waits on that, runs gemm while
    // side continues scanB -> scanC -> fill.
    cudaStream_t s2;
    cudaStreamCreateWithFlags(&s2, cudaStreamNonBlocking);
    cudaEvent_t eFork, eDinv, eCsr;
    cudaEventCreateWithFlags(&eFork, cudaEventDisableTiming);
    cudaEventCreateWithFlags(&eDinv, cudaEventDisableTiming);
    cudaEventCreateWithFlags(&eCsr,  cudaEventDisableTiming);

    k_init<<<(NN + 255) / 256, 256>>>();
    cudaEventRecord(eFork, 0);
    cudaStreamWaitEvent(s2, eFork, 0);

    // side stream: CSR build
    k_count<<<(EE + 255) / 256, 256, 0, s2>>>(ei);
    k_scanA<<<SCAN_NB, SCAN_B, 0, s2>>>();
    cudaEventRecord(eDinv, s2);
    k_scanB<<<1, 64, 0, s2>>>();
    k_scanC<<<SCAN_NB, SCAN_B, 0, s2>>>();
    k_fill<<<(EE + 255) / 256, 256, 0, s2>>>(ei);
    cudaEventRecord(eCsr, s2);

    // main stream: gemm (needs dinv from scanA)
    cudaStreamWaitEvent(0, eDinv, 0);
    k_gemm<<<(NN + BM - 1) / BM, 256>>>(x, W);

    // join: gather needs CSR + hs
    cudaStreamWaitEvent(0, eCsr, 0);
    k_gather<<<(NN * 32 + 255) / 256, 256>>>(batch, b);
    k_head<<<1, 256>>>(batch, fc1_w, fc1_b, aw, ab, cw, cb, out);
}

// round 8
// speedup vs baseline: 1.8626x; 1.1840x over previous
#include <cuda_runtime.h>
#include <cuda_fp16.h>

#define NN 50000
#define EE 800000
#define FF 128
#define HH 128
#define HH2 64
#define TT 8
#define GG 64

#define SCAN_B 1024
#define SCAN_NB ((NN + SCAN_B - 1) / SCAN_B)   // 49

// scratch (static device allocations are allowed)
__device__ __align__(16) float  g_dinv[NN];
__device__ __align__(16) __half g_hsh[NN * HH];   // (x@W)*dinv[row] in fp16
__device__ __align__(16) float  g_pooled[GG * HH];
__device__ int g_cnt[NN];
__device__ int g_cursor[NN];
__device__ int g_rowptr[NN + 1];
__device__ int g_col[EE];
__device__ int g_bsum[SCAN_NB];

__device__ __forceinline__ void red4(float* p, float4 v) {
    asm volatile("red.global.add.v4.f32 [%0], {%1,%2,%3,%4};"
                 :: "l"(p), "f"(v.x), "f"(v.y), "f"(v.z), "f"(v.w) : "memory");
}

__device__ __forceinline__ float to_tf32(float f) {
    unsigned o;
    asm("cvt.rna.tf32.f32 %0, %1;" : "=r"(o) : "f"(f));
    return __uint_as_float(o);
}

__device__ __forceinline__ void mma_tf32(float* d, const unsigned* a, const unsigned* b) {
    asm("mma.sync.aligned.m16n8k8.row.col.f32.tf32.tf32.f32 "
        "{%0,%1,%2,%3},{%4,%5,%6,%7},{%8,%9},{%0,%1,%2,%3};"
        : "+f"(d[0]), "+f"(d[1]), "+f"(d[2]), "+f"(d[3])
        : "r"(a[0]), "r"(a[1]), "r"(a[2]), "r"(a[3]), "r"(b[0]), "r"(b[1]));
}

// -------------------------------------------------------------------------
__global__ void k_init() {
    int i = blockIdx.x * blockDim.x + threadIdx.x;
    if (i < NN) { g_cnt[i] = 0; g_cursor[i] = 0; }
    if (i < GG * HH) g_pooled[i] = 0.0f;
}

__global__ void k_count(const int* __restrict__ ei) {
    int e = blockIdx.x * blockDim.x + threadIdx.x;
    if (e < EE) atomicAdd(&g_cnt[ei[EE + e]], 1);
}

// ---- hierarchical scan -------------------------------------------------
__global__ __launch_bounds__(SCAN_B) void k_scanA() {
    __shared__ int ssum[SCAN_B];
    int tid = threadIdx.x;
    int idx = blockIdx.x * SCAN_B + tid;
    int c = (idx < NN) ? g_cnt[idx] : 0;
    if (idx < NN) g_dinv[idx] = rsqrtf((float)(c + 1));   // +1 self-loop
    ssum[tid] = c;
    __syncthreads();
#pragma unroll
    for (int off = 1; off < SCAN_B; off <<= 1) {
        int v = (tid >= off) ? ssum[tid - off] : 0;
        __syncthreads();
        ssum[tid] += v;
        __syncthreads();
    }
    if (idx < NN) g_rowptr[idx] = ssum[tid] - c;          // local exclusive
    if (tid == SCAN_B - 1) g_bsum[blockIdx.x] = ssum[tid];
}

__global__ __launch_bounds__(64) void k_scanB() {
    __shared__ int s[SCAN_NB];
    int tid = threadIdx.x;
    if (tid < SCAN_NB) s[tid] = g_bsum[tid];
    __syncthreads();
    if (tid == 0) {
        int run = 0;
        for (int i = 0; i < SCAN_NB; i++) { int v = s[i]; s[i] = run; run += v; }
        g_rowptr[NN] = run;
    }
    __syncthreads();
    if (tid < SCAN_NB) g_bsum[tid] = s[tid];
}

__global__ __launch_bounds__(SCAN_B) void k_scanC() {
    int idx = blockIdx.x * SCAN_B + threadIdx.x;
    if (idx < NN && blockIdx.x > 0) g_rowptr[idx] += g_bsum[blockIdx.x];
}

__global__ void k_fill(const int* __restrict__ ei) {
    int e = blockIdx.x * blockDim.x + threadIdx.x;
    if (e < EE) {
        int dst = ei[EE + e];
        int pos = g_rowptr[dst] + atomicAdd(&g_cursor[dst], 1);
        g_col[pos] = ei[e];
    }
}

// -------------------------------------------------------------------------
// hs = (x @ W) * dinv[row], tf32 tensor cores, stored as fp16.
// Block: 256 thr = 8 warps (4x2), tile 128 rows x 128 cols, K chunks of 32.
#define GM 128
#define KC 32
#define XS_STRIDE 36    // bank = (4r+c)%32 = lane -> conflict free
#define WS_STRIDE 136   // bank = (8k+n)%32 distinct -> conflict free
__global__ __launch_bounds__(256) void k_gemm(const float* __restrict__ x,
                                              const float* __restrict__ W) {
    __shared__ float xs[GM * XS_STRIDE];      // 18432 B
    __shared__ float ws[KC * WS_STRIDE];      // 17408 B
    int tid = threadIdx.x;
    int wid = tid >> 5;
    int lane = tid & 31;
    int l4 = lane >> 2;       // groupID 0..7
    int lm4 = lane & 3;       // threadID_in_group 0..3
    int warpM = wid >> 1;     // 0..3 -> rows warpM*32
    int warpN = wid & 1;      // 0..1 -> cols warpN*64
    int row0 = blockIdx.x * GM;

    float acc[2][8][4];
#pragma unroll
    for (int i = 0; i < 2; i++)
#pragma unroll
        for (int j = 0; j < 8; j++)
#pragma unroll
            for (int q = 0; q < 4; q++) acc[i][j][q] = 0.0f;

    for (int kc = 0; kc < FF; kc += KC) {
        // stage x[row0..row0+128)[kc..kc+32) -> xs (tf32)
#pragma unroll
        for (int q = 0; q < 4; q++) {
            int idx = tid + q * 256;        // 0..1023 float4s
            int r = idx >> 3;               // 0..127
            int c4 = idx & 7;               // 0..7
            int gr = row0 + r;
            float4 v = make_float4(0.f, 0.f, 0.f, 0.f);
            if (gr < NN) v = *(const float4*)(x + (size_t)gr * FF + kc + c4 * 4);
            float* d = &xs[r * XS_STRIDE + c4 * 4];
            d[0] = to_tf32(v.x); d[1] = to_tf32(v.y);
            d[2] = to_tf32(v.z); d[3] = to_tf32(v.w);
        }
        // stage W[kc..kc+32)[0..128) -> ws (tf32)
#pragma unroll
        for (int q = 0; q < 4; q++) {
            int idx = tid + q * 256;        // 0..1023
            int r = idx >> 5;               // 0..31
            int c4 = idx & 31;              // 0..31
            float4 v = *(const float4*)(W + (size_t)(kc + r) * HH + c4 * 4);
            float* d = &ws[r * WS_STRIDE + c4 * 4];
            d[0] = to_tf32(v.x); d[1] = to_tf32(v.y);
            d[2] = to_tf32(v.z); d[3] = to_tf32(v.w);
        }
        __syncthreads();

#pragma unroll
        for (int ks = 0; ks < KC; ks += 8) {
            // A fragments: 2 M-frags (rows warpM*32 + 16i)
            unsigned afr[2][4];
#pragma unroll
            for (int i = 0; i < 2; i++) {
                int rA = warpM * 32 + i * 16;
                afr[i][0] = __float_as_uint(xs[(rA + l4)     * XS_STRIDE + ks + lm4]);
                afr[i][1] = __float_as_uint(xs[(rA + l4 + 8) * XS_STRIDE + ks + lm4]);
                afr[i][2] = __float_as_uint(xs[(rA + l4)     * XS_STRIDE + ks + lm4 + 4]);
                afr[i][3] = __float_as_uint(xs[(rA + l4 + 8) * XS_STRIDE + ks + lm4 + 4]);
            }
            // B fragments: 8 N-frags (cols warpN*64 + 8j)
#pragma unroll
            for (int j = 0; j < 8; j++) {
                int n0 = warpN * 64 + j * 8;
                unsigned bfr[2];
                bfr[0] = __float_as_uint(ws[(ks + lm4)     * WS_STRIDE + n0 + l4]);
                bfr[1] = __float_as_uint(ws[(ks + lm4 + 4) * WS_STRIDE + n0 + l4]);
                mma_tf32(acc[0][j], afr[0], bfr);
                mma_tf32(acc[1][j], afr[1], bfr);
            }
        }
        __syncthreads();
    }

    // epilogue: scale by dinv[row], pack fp16
#pragma unroll
    for (int i = 0; i < 2; i++) {
#pragma unroll
        for (int h = 0; h < 2; h++) {
            int r = row0 + warpM * 32 + i * 16 + h * 8 + l4;
            if (r < NN) {
                float d = g_dinv[r];
#pragma unroll
                for (int j = 0; j < 8; j++) {
                    int col = warpN * 64 + j * 8 + 2 * lm4;
                    __half2 hv = __floats2half2_rn(acc[i][j][2 * h] * d,
                                                   acc[i][j][2 * h + 1] * d);
                    *(__half2*)(g_hsh + (size_t)r * HH + col) = hv;
                }
            }
        }
    }
}

// -------------------------------------------------------------------------
// CSR gather + fused pool: one warp per dst node, fp16 operands, fp32 acc.
__global__ __launch_bounds__(256) void k_gather(const int* __restrict__ batch,
                                                const float* __restrict__ b) {
    int w = (blockIdx.x * blockDim.x + threadIdx.x) >> 5;
    if (w >= NN) return;
    int lane = threadIdx.x & 31;
    size_t coff = (size_t)lane * 4;

    uint2 us = __ldg((const uint2*)(g_hsh + (size_t)w * HH + coff));
    float2 f0 = __half22float2(*(__half2*)&us.x);
    float2 f1 = __half22float2(*(__half2*)&us.y);
    float4 a0 = make_float4(f0.x, f0.y, f1.x, f1.y);
    float4 a1 = make_float4(0.f, 0.f, 0.f, 0.f);

    int beg = g_rowptr[w], end = g_rowptr[w + 1];
    int e = beg;
    for (; e + 2 <= end; e += 2) {
        int s0 = __ldg(g_col + e);
        int s1 = __ldg(g_col + e + 1);
        uint2 u0 = __ldg((const uint2*)(g_hsh + (size_t)s0 * HH + coff));
        uint2 u1 = __ldg((const uint2*)(g_hsh + (size_t)s1 * HH + coff));
        float2 p0 = __half22float2(*(__half2*)&u0.x);
        float2 p1 = __half22float2(*(__half2*)&u0.y);
        float2 q0 = __half22float2(*(__half2*)&u1.x);
        float2 q1 = __half22float2(*(__half2*)&u1.y);
        a0.x += p0.x; a0.y += p0.y; a0.z += p1.x; a0.w += p1.y;
        a1.x += q0.x; a1.y += q0.y; a1.z += q1.x; a1.w += q1.y;
    }
    if (e < end) {
        int s0 = __ldg(g_col + e);
        uint2 u0 = __ldg((const uint2*)(g_hsh + (size_t)s0 * HH + coff));
        float2 p0 = __half22float2(*(__half2*)&u0.x);
        float2 p1 = __half22float2(*(__half2*)&u0.y);
        a0.x += p0.x; a0.y += p0.y; a0.z += p1.x; a0.w += p1.y;
    }
    float d = g_dinv[w];
    float4 bb = *(const float4*)(b + coff);
    float4 p;
    p.x = fmaxf((a0.x + a1.x) * d + bb.x, 0.f);
    p.y = fmaxf((a0.y + a1.y) * d + bb.y, 0.f);
    p.z = fmaxf((a0.z + a1.z) * d + bb.z, 0.f);
    p.w = fmaxf((a0.w + a1.w) * d + bb.w, 0.f);
    int g = __ldg(batch + w);
    red4(g_pooled + (size_t)g * HH + coff, p);
}

// -------------------------------------------------------------------------
__global__ __launch_bounds__(256) void k_head(const int* __restrict__ batch,
                                              const float* __restrict__ fc1_w,
                                              const float* __restrict__ fc1_b,
                                              const float* __restrict__ aw,
                                              const float* __restrict__ ab,
                                              const float* __restrict__ cw,
                                              const float* __restrict__ cb,
                                              float* __restrict__ out) {
    __shared__ float s_gs[GG * HH];
    __shared__ float s_z[GG * HH2];
    __shared__ float s_logit[GG * TT];
    __shared__ int s_lb[GG + 1];
    int tid = threadIdx.x;

    if (tid <= GG) {
        int g = tid, lo = 0, hi = NN;
        while (lo < hi) {
            int mid = (lo + hi) >> 1;
            if (batch[mid] < g) lo = mid + 1; else hi = mid;
        }
        s_lb[tid] = lo;
    }
    __syncthreads();

    for (int i = tid; i < GG * HH; i += 256) {
        int g = i >> 7;
        float c = (float)(s_lb[g + 1] - s_lb[g]);
        s_gs[i] = g_pooled[i] / fmaxf(c, 1.0f);
    }
    __syncthreads();

    for (int o = tid; o < GG * HH2; o += 256) {
        int g = o >> 6, j = o & 63;
        float s = fc1_b[j];
        const float* gr = &s_gs[g * HH];
#pragma unroll 8
        for (int k = 0; k < HH; k++) s += gr[k] * fc1_w[k * HH2 + j];
        s_z[o] = fmaxf(s, 0.f);
    }
    __syncthreads();

    for (int o = tid; o < GG * TT; o += 256) {
        int g = o >> 3, t = o & 7;
        float s = ab[t];
        const float* zr = &s_z[g * HH2];
#pragma unroll
        for (int k = 0; k < HH2; k++) s += zr[k] * aw[k * TT + t];
        s_logit[o] = s;
    }
    if (tid < GG) {
        float s = cb[0];
        const float* zr = &s_z[tid * HH2];
#pragma unroll
        for (int k = 0; k < HH2; k++) s += zr[k] * cw[k];
        out[GG * TT + tid] = s;
    }
    __syncthreads();

    if (tid < GG) {
        float m = -1e30f;
#pragma unroll
        for (int t = 0; t < TT; t++) m = fmaxf(m, s_logit[tid * TT + t]);
        float e[TT], sum = 0.f;
#pragma unroll
        for (int t = 0; t < TT; t++) { e[t] = expf(s_logit[tid * TT + t] - m); sum += e[t]; }
        float inv = 1.0f / sum;
#pragma unroll
        for (int t = 0; t < TT; t++) out[tid * TT + t] = e[t] * inv;
    }
}

// -------------------------------------------------------------------------
extern "C" void kernel_launch(void* const* d_in, const int* in_sizes, int n_in,
                              void* d_out, int out_size) {
    const float* x     = (const float*)d_in[0];
    const int*   ei    = (const int*)d_in[1];
    const int*   batch = (const int*)d_in[2];
    const float* W     = (const float*)d_in[3];
    const float* b     = (const float*)d_in[4];
    const float* fc1_w = (const float*)d_in[5];
    const float* fc1_b = (const float*)d_in[6];
    const float* aw    = (const float*)d_in[7];
    const float* ab    = (const float*)d_in[8];
    const float* cw    = (const float*)d_in[9];
    const float* cb    = (const float*)d_in[10];
    float* out = (float*)d_out;

    cudaStream_t s2;
    cudaStreamCreateWithFlags(&s2, cudaStreamNonBlocking);
    cudaEvent_t eFork, eDinv, eCsr;
    cudaEventCreateWithFlags(&eFork, cudaEventDisableTiming);
    cudaEventCreateWithFlags(&eDinv, cudaEventDisableTiming);
    cudaEventCreateWithFlags(&eCsr,  cudaEventDisableTiming);

    k_init<<<(NN + 255) / 256, 256>>>();
    cudaEventRecord(eFork, 0);
    cudaStreamWaitEvent(s2, eFork, 0);

    // side stream: CSR build
    k_count<<<(EE + 255) / 256, 256, 0, s2>>>(ei);
    k_scanA<<<SCAN_NB, SCAN_B, 0, s2>>>();
    cudaEventRecord(eDinv, s2);
    k_scanB<<<1, 64, 0, s2>>>();
    k_scanC<<<SCAN_NB, SCAN_B, 0, s2>>>();
    k_fill<<<(EE + 255) / 256, 256, 0, s2>>>(ei);
    cudaEventRecord(eCsr, s2);

    // main stream: gemm (needs dinv from scanA)
    cudaStreamWaitEvent(0, eDinv, 0);
    k_gemm<<<(NN + GM - 1) / GM, 256>>>(x, W);

    // join: gather needs CSR + hs
    cudaStreamWaitEvent(0, eCsr, 0);
    k_gather<<<(NN * 32 + 255) / 256, 256>>>(batch, b);
    k_head<<<1, 256>>>(batch, fc1_w, fc1_b, aw, ab, cw, cb, out);
}